// round 6
// baseline (speedup 1.0000x reference)
#include <cuda_runtime.h>
#include <cuda_bf16.h>
#include <math.h>
#include <stdint.h>

#define NN 50000
#define EE 500000
#define NB_SCAN ((NN + 255) / 256)   // 196

// ---------------- scratch ----------------
__device__ __nv_bfloat16 g_nfh[(size_t)NN * 256];   // node features hi/lo planes
__device__ __nv_bfloat16 g_nfl[(size_t)NN * 256];
__device__ __nv_bfloat16 g_efah[(size_t)EE * 64];   // efeats split (layer-0 A)
__device__ __nv_bfloat16 g_efal[(size_t)EE * 64];
__device__ __nv_bfloat16 g_efbh[(size_t)EE * 128];  // layer-0 ef output planes (layer-1 A)
__device__ __nv_bfloat16 g_efbl[(size_t)EE * 128];
__device__ float    g_node_out[(size_t)NN * 512];   // [f_ni(128) | f_nj(128) | h_src(256)]
__device__ float    g_elog[(size_t)EE * 4];
__device__ float    g_bcat[512];
__device__ __nv_bfloat16 g_btn_hi[512 * 256];
__device__ __nv_bfloat16 g_btn_lo[512 * 256];
__device__ __nv_bfloat16 g_bte_hi[128 * 128];
__device__ __nv_bfloat16 g_bte_lo[128 * 128];
// CSR by dst
__device__ int g_deg[NN];
__device__ int g_offs[NN + 1];
__device__ int g_cursor[NN];
__device__ int g_eidx[EE];
__device__ int g_bsum[256];

// ---------------- helpers ----------------
__device__ __forceinline__ uint32_t smem_u32(const void* p) {
    uint32_t a;
    asm("{ .reg .u64 t; cvta.to.shared.u64 t, %1; cvt.u32.u64 %0, t; }" : "=r"(a) : "l"(p));
    return a;
}
__device__ __forceinline__ unsigned lds32(uint32_t a) {
    unsigned v;
    asm volatile("ld.shared.b32 %0, [%1];" : "=r"(v) : "r"(a));
    return v;
}
#define CP_ASYNC16Z(dst, src, pred) \
    asm volatile("cp.async.ca.shared.global [%0], [%1], 16, %2;" \
                 :: "r"(dst), "l"(src), "r"((pred) ? 16 : 0) : "memory")
#define CP_COMMIT() asm volatile("cp.async.commit_group;" ::: "memory")
#define CP_WAIT0()  asm volatile("cp.async.wait_group 0;" ::: "memory")

__device__ __forceinline__ void mma_bf16(float& d0, float& d1, float& d2, float& d3,
                                         unsigned a0, unsigned a1, unsigned a2, unsigned a3,
                                         unsigned b0, unsigned b1) {
    asm volatile(
        "mma.sync.aligned.m16n8k16.row.col.f32.bf16.bf16.f32 "
        "{%0,%1,%2,%3}, {%4,%5,%6,%7}, {%8,%9}, {%0,%1,%2,%3};"
        : "+f"(d0), "+f"(d1), "+f"(d2), "+f"(d3)
        : "r"(a0), "r"(a1), "r"(a2), "r"(a3), "r"(b0), "r"(b1));
}
__device__ __forceinline__ void split2(float a, float b, unsigned& hi, unsigned& lo) {
    __nv_bfloat16 ah = __float2bfloat16_rn(a), bh = __float2bfloat16_rn(b);
    __nv_bfloat16 al = __float2bfloat16_rn(a - __bfloat162float(ah));
    __nv_bfloat16 bl = __float2bfloat16_rn(b - __bfloat162float(bh));
    hi = (unsigned)__bfloat16_as_ushort(ah) | ((unsigned)__bfloat16_as_ushort(bh) << 16);
    lo = (unsigned)__bfloat16_as_ushort(al) | ((unsigned)__bfloat16_as_ushort(bl) << 16);
}
__device__ __forceinline__ float elu_f(float v)   { return v > 0.f ? v : expm1f(v); }
__device__ __forceinline__ float lrelu_f(float v) { return v > 0.f ? v : 0.01f * v; }

// ---------------- smem layout (bytes) ----------------
#define AHI    0
#define ALO    10240
#define BHI    20480
#define BLO    30720
#define BUFSZ  40960
#define NODE_BIAS 81920
#define NODE_SMEM (81920 + 2048)
#define EST      0
#define ESRC     81920
#define EDST     82432
#define EBIAS    82944
#define EATTN    83456
#define ELSH     83968
#define EDGE_SMEM 86016

// ---------------- producers write bf16 planes ----------------
__global__ void k_embed(const int* __restrict__ node_types,
                        const float* __restrict__ embed,
                        __nv_bfloat16* __restrict__ nfh, __nv_bfloat16* __restrict__ nfl) {
    int i = blockIdx.x * 256 + threadIdx.x;
    if (i < NN * 32) {
        int n = i >> 5, c4 = (i & 31) * 4;
        float4 v = *(const float4*)(embed + node_types[n] * 128 + c4);
        unsigned h0, l0, h1, l1;
        split2(v.x, v.y, h0, l0);
        split2(v.z, v.w, h1, l1);
        size_t o = (size_t)n * 128 + c4;
        *(uint2*)(nfh + o) = make_uint2(h0, h1);
        *(uint2*)(nfl + o) = make_uint2(l0, l1);
    }
}

__global__ void k_split_ef(const float* __restrict__ ef,
                           __nv_bfloat16* __restrict__ efh, __nv_bfloat16* __restrict__ efl) {
    int i = blockIdx.x * 256 + threadIdx.x;
    if (i < EE * 16) {
        size_t j = (size_t)i * 4;
        float4 v = *(const float4*)(ef + j);
        unsigned h0, l0, h1, l1;
        split2(v.x, v.y, h0, l0);
        split2(v.z, v.w, h1, l1);
        *(uint2*)(efh + j) = make_uint2(h0, h1);
        *(uint2*)(efl + j) = make_uint2(l0, l1);
    }
}

__global__ void k_prep(const float* __restrict__ Wni, const float* __restrict__ Wnj,
                       const float* __restrict__ Wsrc, const float* __restrict__ bsrc,
                       const float* __restrict__ Wfij,
                       float* __restrict__ bcat,
                       __nv_bfloat16* __restrict__ btn_hi, __nv_bfloat16* __restrict__ btn_lo,
                       __nv_bfloat16* __restrict__ bte_hi, __nv_bfloat16* __restrict__ bte_lo,
                       int in_n, int in_e) {
    int i = blockIdx.x * 256 + threadIdx.x;
    int nn = 512 * in_n;
    if (i < nn) {
        int n = i / in_n, k = i - n * in_n;
        float v;
        if (n < 128)      v = Wni[k * 128 + n];
        else if (n < 256) v = Wnj[k * 128 + (n - 128)];
        else              v = Wsrc[k * 256 + (n - 256)];
        __nv_bfloat16 h = __float2bfloat16_rn(v);
        __nv_bfloat16 l = __float2bfloat16_rn(v - __bfloat162float(h));
        btn_hi[(size_t)n * in_n + k] = h;
        btn_lo[(size_t)n * in_n + k] = l;
    } else if (i < nn + 128 * in_e) {
        int j = i - nn;
        int n = j / in_e, k = j - n * in_e;
        float v = Wfij[k * 128 + n];
        __nv_bfloat16 h = __float2bfloat16_rn(v);
        __nv_bfloat16 l = __float2bfloat16_rn(v - __bfloat162float(h));
        bte_hi[(size_t)n * in_e + k] = h;
        bte_lo[(size_t)n * in_e + k] = l;
    }
    if (i < 512) bcat[i] = (i < 256) ? 0.f : bsrc[i - 256];
}

// ---------------- CSR build ----------------
__global__ void k_zero_deg(int* __restrict__ deg) {
    int i = blockIdx.x * 256 + threadIdx.x;
    if (i < NN) deg[i] = 0;
}
__global__ void k_hist(const int* __restrict__ dst, int* __restrict__ deg) {
    int e = blockIdx.x * 256 + threadIdx.x;
    if (e < EE) atomicAdd(&deg[dst[e]], 1);
}
__global__ void k_scanA(const int* __restrict__ deg, int* __restrict__ bsum) {
    __shared__ int sh[256];
    int i = blockIdx.x * 256 + threadIdx.x;
    sh[threadIdx.x] = (i < NN) ? deg[i] : 0;
    __syncthreads();
    for (int o = 128; o > 0; o >>= 1) {
        if (threadIdx.x < o) sh[threadIdx.x] += sh[threadIdx.x + o];
        __syncthreads();
    }
    if (threadIdx.x == 0) bsum[blockIdx.x] = sh[0];
}
__global__ void k_scanB(int* __restrict__ bsum) {
    __shared__ int sh[256];
    int t = threadIdx.x;
    int v = (t < NB_SCAN) ? bsum[t] : 0;
    sh[t] = v;
    __syncthreads();
    for (int o = 1; o < 256; o <<= 1) {
        int add = (t >= o) ? sh[t - o] : 0;
        __syncthreads();
        sh[t] += add;
        __syncthreads();
    }
    if (t < NB_SCAN) bsum[t] = sh[t] - v;
}
__global__ void k_scanC(const int* __restrict__ deg, const int* __restrict__ bsum,
                        int* __restrict__ offs, int* __restrict__ cursor) {
    __shared__ int sh[256];
    int i = blockIdx.x * 256 + threadIdx.x;
    int t = threadIdx.x;
    int v = (i < NN) ? deg[i] : 0;
    sh[t] = v;
    __syncthreads();
    for (int o = 1; o < 256; o <<= 1) {
        int add = (t >= o) ? sh[t - o] : 0;
        __syncthreads();
        sh[t] += add;
        __syncthreads();
    }
    if (i < NN) {
        int ex = bsum[blockIdx.x] + sh[t] - v;
        offs[i] = ex;
        cursor[i] = ex;
    }
    if (i == 0) offs[NN] = EE;
}
__global__ void k_scatter(const int* __restrict__ dst, int* __restrict__ cursor,
                          int* __restrict__ eidx) {
    int e = blockIdx.x * 256 + threadIdx.x;
    if (e < EE) {
        int pos = atomicAdd(&cursor[dst[e]], 1);
        eidx[pos] = e;
    }
}

// ---------------- pure cp.async GEMM mainloop ----------------
__device__ __forceinline__ void tile_load(
    uint32_t sb, int buf,
    const __nv_bfloat16* __restrict__ Ah, const __nv_bfloat16* __restrict__ Al,
    int row0, int M,
    const __nv_bfloat16* __restrict__ Bh, const __nv_bfloat16* __restrict__ Bl,
    int n0, int K, int k0) {
    int tid = threadIdx.x;
    uint32_t bo = sb + buf * BUFSZ;
#pragma unroll
    for (int i = 0; i < 2; i++) {
        int c = tid + i * 256;
        int r = c >> 2, k16 = c & 3;
        // A
        int arow = row0 + r;
        size_t ga = (size_t)arow * K + k0 + k16 * 8;
        uint32_t da = bo + AHI + r * 80 + k16 * 16;
        int av = arow < M;
        CP_ASYNC16Z(da, Ah + ga, av);
        CP_ASYNC16Z(da + (ALO - AHI), Al + ga, av);
        // B (rows always valid: 128-row panels within 512/128-wide weights)
        size_t gb = (size_t)(n0 + r) * K + k0 + k16 * 8;
        uint32_t db = bo + BHI + r * 80 + k16 * 16;
        CP_ASYNC16Z(db, Bh + gb, 1);
        CP_ASYNC16Z(db + (BLO - BHI), Bl + gb, 1);
    }
}

__device__ __forceinline__ void mma_compute(uint32_t sb, int buf, float acc[2][8][4]) {
    int tid = threadIdx.x, lane = tid & 31, wid = tid >> 5;
    int g = lane >> 2, tig = lane & 3;
    int wm = wid & 3, wn = wid >> 2;
    uint32_t bo = sb + buf * BUFSZ;
#pragma unroll
    for (int ks = 0; ks < 2; ks++) {
        unsigned ahr[2][4], alr[2][4];
        uint32_t abase = bo + AHI + (wm * 32 + g) * 80 + ks * 32 + tig * 4;
#pragma unroll
        for (int mt = 0; mt < 2; mt++) {
            uint32_t a0 = abase + mt * (16 * 80);
            ahr[mt][0] = lds32(a0);
            ahr[mt][1] = lds32(a0 + 8 * 80);
            ahr[mt][2] = lds32(a0 + 16);
            ahr[mt][3] = lds32(a0 + 8 * 80 + 16);
            uint32_t a0l = a0 + (ALO - AHI);
            alr[mt][0] = lds32(a0l);
            alr[mt][1] = lds32(a0l + 8 * 80);
            alr[mt][2] = lds32(a0l + 16);
            alr[mt][3] = lds32(a0l + 8 * 80 + 16);
        }
        uint32_t bbase = bo + BHI + (wn * 64 + g) * 80 + ks * 32 + tig * 4;
#pragma unroll
        for (int nt = 0; nt < 8; nt++) {
            uint32_t b0a = bbase + nt * (8 * 80);
            unsigned bh0 = lds32(b0a), bh1 = lds32(b0a + 16);
            unsigned bl0 = lds32(b0a + (BLO - BHI)), bl1 = lds32(b0a + (BLO - BHI) + 16);
#pragma unroll
            for (int mt = 0; mt < 2; mt++) {
                float* d = acc[mt][nt];
                mma_bf16(d[0], d[1], d[2], d[3],
                         ahr[mt][0], ahr[mt][1], ahr[mt][2], ahr[mt][3], bh0, bh1);
                mma_bf16(d[0], d[1], d[2], d[3],
                         ahr[mt][0], ahr[mt][1], ahr[mt][2], ahr[mt][3], bl0, bl1);
                mma_bf16(d[0], d[1], d[2], d[3],
                         alr[mt][0], alr[mt][1], alr[mt][2], alr[mt][3], bh0, bh1);
            }
        }
    }
}

__device__ __forceinline__ void mma_mainloop(
    uint32_t sb,
    const __nv_bfloat16* __restrict__ Ah, const __nv_bfloat16* __restrict__ Al,
    const __nv_bfloat16* __restrict__ Bh, const __nv_bfloat16* __restrict__ Bl,
    int row0, int n0, int M, int K, float acc[2][8][4]) {
    int nst = K >> 5;
    tile_load(sb, 0, Ah, Al, row0, M, Bh, Bl, n0, K, 0);
    CP_COMMIT();
    CP_WAIT0();
    __syncthreads();
    for (int s = 0; s < nst; s++) {
        int buf = s & 1;
        bool more = (s + 1) < nst;
        if (more) {
            tile_load(sb, buf ^ 1, Ah, Al, row0, M, Bh, Bl, n0, K, (s + 1) * 32);
            CP_COMMIT();
        }
        mma_compute(sb, buf, acc);
        if (more) CP_WAIT0();
        __syncthreads();
    }
}

// ---------------- node GEMM ----------------
__global__ __launch_bounds__(256, 2) void gemm_node_mma(
    const __nv_bfloat16* __restrict__ Ah, const __nv_bfloat16* __restrict__ Al,
    const __nv_bfloat16* __restrict__ Bth, const __nv_bfloat16* __restrict__ Btl,
    const float* __restrict__ bias, float* __restrict__ Cout, int M, int K) {
    extern __shared__ __align__(16) char smem[];
    uint32_t sb = smem_u32(smem);
    float* bsm = (float*)(smem + NODE_BIAS);
    int tid = threadIdx.x;
    ((float2*)bsm)[tid] = ((const float2*)bias)[tid];

    int row0 = blockIdx.x * 128, n0 = blockIdx.y * 128;
    float acc[2][8][4];
#pragma unroll
    for (int mt = 0; mt < 2; mt++)
#pragma unroll
        for (int nt = 0; nt < 8; nt++)
#pragma unroll
            for (int q = 0; q < 4; q++) acc[mt][nt][q] = 0.f;

    mma_mainloop(sb, Ah, Al, Bth, Btl, row0, n0, M, K, acc);

    int lane = tid & 31, wid = tid >> 5;
    int g = lane >> 2, tig = lane & 3;
    int wm = wid & 3, wn = wid >> 2;
#pragma unroll
    for (int mt = 0; mt < 2; mt++) {
        int r0 = row0 + wm * 32 + mt * 16 + g;
#pragma unroll
        for (int nt = 0; nt < 8; nt++) {
            int cc = n0 + wn * 64 + nt * 8 + 2 * tig;
            float b0 = bsm[cc], b1 = bsm[cc + 1];
            float* d = acc[mt][nt];
            if (r0 < M)
                *(float2*)(Cout + (size_t)r0 * 512 + cc) = make_float2(d[0] + b0, d[1] + b1);
            if (r0 + 8 < M)
                *(float2*)(Cout + (size_t)(r0 + 8) * 512 + cc) = make_float2(d[2] + b0, d[3] + b1);
        }
    }
}

// ---------------- edge GEMM fused epilogue ----------------
// mode 0: write ef as bf16 hi/lo planes (stride 128); mode 1: write fp32
__global__ __launch_bounds__(256, 2) void gemm_edge_mma(
    const __nv_bfloat16* __restrict__ Ah, const __nv_bfloat16* __restrict__ Al,
    const __nv_bfloat16* __restrict__ Bth, const __nv_bfloat16* __restrict__ Btl,
    const float* __restrict__ node_out,
    const int* __restrict__ src, const int* __restrict__ dst,
    const float* __restrict__ bias, const float* __restrict__ attn,
    float* __restrict__ ef32,
    __nv_bfloat16* __restrict__ efoh, __nv_bfloat16* __restrict__ efol,
    float* __restrict__ elog, int M, int K, int mode) {
    extern __shared__ __align__(16) char smem[];
    uint32_t sb = smem_u32(smem);
    float* stage = (float*)(smem + EST);
    int*   ssh = (int*)(smem + ESRC);
    int*   dsh = (int*)(smem + EDST);
    float* bsh = (float*)(smem + EBIAS);
    float* ash = (float*)(smem + EATTN);
    float* lsh = (float*)(smem + ELSH);

    int tid = threadIdx.x;
    int e0 = blockIdx.x * 128;
    if (tid < 128) {
        int e = e0 + tid;
        ssh[tid] = (e < M) ? src[e] : 0;
        dsh[tid] = (e < M) ? dst[e] : 0;
        bsh[tid] = bias[tid];
        ash[tid] = attn[tid];
    }

    float acc[2][8][4];
#pragma unroll
    for (int mt = 0; mt < 2; mt++)
#pragma unroll
        for (int nt = 0; nt < 8; nt++)
#pragma unroll
            for (int q = 0; q < 4; q++) acc[mt][nt][q] = 0.f;

    mma_mainloop(sb, Ah, Al, Bth, Btl, e0, 0, M, K, acc);

    int lane = tid & 31, wid = tid >> 5;
    int g = lane >> 2, tig = lane & 3;
    int wm = wid & 3, wn = wid >> 2;
#pragma unroll
    for (int mt = 0; mt < 2; mt++) {
        int r = wm * 32 + mt * 16 + g;
#pragma unroll
        for (int nt = 0; nt < 8; nt++) {
            int cc = wn * 64 + nt * 8 + 2 * tig;
            float* d = acc[mt][nt];
            *(float2*)&stage[r * 132 + cc] = make_float2(d[0], d[1]);
            *(float2*)&stage[(r + 8) * 132 + cc] = make_float2(d[2], d[3]);
        }
    }
    __syncthreads();

    {
        int r = tid & 127, hc = tid >> 7;
        int e = e0 + r;
        if (e < M) {
            int si = ssh[r], dj = dsh[r];
            const float* pni = node_out + (size_t)si * 512 + hc * 64;
            const float* pnj = node_out + (size_t)dj * 512 + 128 + hc * 64;
            const float* sp = stage + r * 132 + hc * 64;
            float part[2] = {0.f, 0.f};
#pragma unroll
            for (int q = 0; q < 16; q++) {
                int c = hc * 64 + q * 4;
                float4 sv = *(const float4*)(sp + q * 4);
                float4 a = *(const float4*)(pni + q * 4);
                float4 b = *(const float4*)(pnj + q * 4);
                float4 o;
                float v;
                v = sv.x + a.x + b.x + bsh[c + 0];
                v = lrelu_f(v); part[q >> 3] += v * ash[c + 0]; o.x = elu_f(v);
                v = sv.y + a.y + b.y + bsh[c + 1];
                v = lrelu_f(v); part[q >> 3] += v * ash[c + 1]; o.y = elu_f(v);
                v = sv.z + a.z + b.z + bsh[c + 2];
                v = lrelu_f(v); part[q >> 3] += v * ash[c + 2]; o.z = elu_f(v);
                v = sv.w + a.w + b.w + bsh[c + 3];
                v = lrelu_f(v); part[q >> 3] += v * ash[c + 3]; o.w = elu_f(v);
                if (mode == 0) {
                    unsigned h0, l0, h1, l1;
                    split2(o.x, o.y, h0, l0);
                    split2(o.z, o.w, h1, l1);
                    size_t oo = (size_t)e * 128 + c;
                    *(uint2*)(efoh + oo) = make_uint2(h0, h1);
                    *(uint2*)(efol + oo) = make_uint2(l0, l1);
                } else {
                    *(float4*)(ef32 + (size_t)e * 128 + c) = o;
                }
            }
            lsh[r * 4 + hc * 2 + 0] = part[0];
            lsh[r * 4 + hc * 2 + 1] = part[1];
        }
    }
    __syncthreads();

    for (int t = tid; t < 512; t += 256) {
        int r2 = t >> 2, h = t & 3;
        int e2 = e0 + r2;
        if (e2 < M) elog[(size_t)e2 * 4 + h] = lsh[r2 * 4 + h];
    }
}

// ---------------- CSR aggregation ----------------
// mode 0: write bf16 hi/lo planes (stride 256); mode 1: write fp32
__global__ __launch_bounds__(256) void k_aggr(
    const int* __restrict__ srcs, const int* __restrict__ eidx,
    const int* __restrict__ offs, const float* __restrict__ elog,
    const float* __restrict__ node_out,
    float* __restrict__ out32,
    __nv_bfloat16* __restrict__ outh, __nv_bfloat16* __restrict__ outl, int mode) {
    int node = (blockIdx.x * 256 + threadIdx.x) >> 5;
    int lane = threadIdx.x & 31;
    if (node >= NN) return;
    int beg = offs[node], end = offs[node + 1];

    float4 mx = make_float4(-1e30f, -1e30f, -1e30f, -1e30f);
    for (int j = beg + lane; j < end; j += 32) {
        int e = eidx[j];
        float4 l = *(const float4*)(elog + (size_t)e * 4);
        mx.x = fmaxf(mx.x, l.x); mx.y = fmaxf(mx.y, l.y);
        mx.z = fmaxf(mx.z, l.z); mx.w = fmaxf(mx.w, l.w);
    }
#pragma unroll
    for (int o = 16; o > 0; o >>= 1) {
        mx.x = fmaxf(mx.x, __shfl_xor_sync(0xFFFFFFFFu, mx.x, o));
        mx.y = fmaxf(mx.y, __shfl_xor_sync(0xFFFFFFFFu, mx.y, o));
        mx.z = fmaxf(mx.z, __shfl_xor_sync(0xFFFFFFFFu, mx.z, o));
        mx.w = fmaxf(mx.w, __shfl_xor_sync(0xFFFFFFFFu, mx.w, o));
    }
    int h = lane >> 3;
    float mh = (h == 0) ? mx.x : (h == 1) ? mx.y : (h == 2) ? mx.z : mx.w;

    float acc[8] = {0.f, 0.f, 0.f, 0.f, 0.f, 0.f, 0.f, 0.f};
    float ssum = 0.f;
    int j = beg;
    for (; j + 1 < end; j += 2) {
        int ea = eidx[j], eb = eidx[j + 1];
        int sa = srcs[ea], sbn = srcs[eb];
        float la = elog[(size_t)ea * 4 + h], lb = elog[(size_t)eb * 4 + h];
        const float4* pa = (const float4*)(node_out + (size_t)sa * 512 + 256) + lane * 2;
        const float4* pb = (const float4*)(node_out + (size_t)sbn * 512 + 256) + lane * 2;
        float4 a0 = pa[0], a1 = pa[1];
        float4 b0 = pb[0], b1 = pb[1];
        float wa = expf(la - mh), wb = expf(lb - mh);
        ssum += wa + wb;
        acc[0] += wa * a0.x + wb * b0.x; acc[1] += wa * a0.y + wb * b0.y;
        acc[2] += wa * a0.z + wb * b0.z; acc[3] += wa * a0.w + wb * b0.w;
        acc[4] += wa * a1.x + wb * b1.x; acc[5] += wa * a1.y + wb * b1.y;
        acc[6] += wa * a1.z + wb * b1.z; acc[7] += wa * a1.w + wb * b1.w;
    }
    if (j < end) {
        int e = eidx[j];
        float w = expf(elog[(size_t)e * 4 + h] - mh);
        ssum += w;
        const float4* hp = (const float4*)(node_out + (size_t)srcs[e] * 512 + 256) + lane * 2;
        float4 v0 = hp[0], v1 = hp[1];
        acc[0] += w * v0.x; acc[1] += w * v0.y; acc[2] += w * v0.z; acc[3] += w * v0.w;
        acc[4] += w * v1.x; acc[5] += w * v1.y; acc[6] += w * v1.z; acc[7] += w * v1.w;
    }
    float inv = (end > beg) ? 1.f / ssum : 0.f;
    float o[8];
#pragma unroll
    for (int q = 0; q < 8; q++) o[q] = elu_f(acc[q] * inv);
    if (mode == 0) {
        unsigned hh[4], ll[4];
        split2(o[0], o[1], hh[0], ll[0]); split2(o[2], o[3], hh[1], ll[1]);
        split2(o[4], o[5], hh[2], ll[2]); split2(o[6], o[7], hh[3], ll[3]);
        size_t oo = (size_t)node * 256 + lane * 8;
        *(uint4*)(outh + oo) = make_uint4(hh[0], hh[1], hh[2], hh[3]);
        *(uint4*)(outl + oo) = make_uint4(ll[0], ll[1], ll[2], ll[3]);
    } else {
        float* op = out32 + (size_t)node * 256 + lane * 8;
        *(float4*)op = make_float4(o[0], o[1], o[2], o[3]);
        *(float4*)(op + 4) = make_float4(o[4], o[5], o[6], o[7]);
    }
}

// ---------------- host ----------------
extern "C" void kernel_launch(void* const* d_in, const int* in_sizes, int n_in,
                              void* d_out, int out_size) {
    const int*   node_types = (const int*)d_in[0];
    const int*   src        = (const int*)d_in[1];
    const int*   dst        = (const int*)d_in[2];
    const float* efeats     = (const float*)d_in[3];
    const float* embed      = (const float*)d_in[4];
    const float* W_src[2] = {(const float*)d_in[5],  (const float*)d_in[12]};
    const float* b_src[2] = {(const float*)d_in[6],  (const float*)d_in[13]};
    const float* W_ni[2]  = {(const float*)d_in[7],  (const float*)d_in[14]};
    const float* W_nj[2]  = {(const float*)d_in[8],  (const float*)d_in[15]};
    const float* W_fij[2] = {(const float*)d_in[9],  (const float*)d_in[16]};
    const float* attn[2]  = {(const float*)d_in[10], (const float*)d_in[17]};
    const float* bias[2]  = {(const float*)d_in[11], (const float*)d_in[18]};

    float *node_out, *elog, *bcat;
    int *deg, *offs, *cursor, *eidx, *bsum;
    __nv_bfloat16 *nfh, *nfl, *efah, *efal, *efbh, *efbl, *btnh, *btnl, *bteh, *btel;
    cudaGetSymbolAddress((void**)&nfh, g_nfh);
    cudaGetSymbolAddress((void**)&nfl, g_nfl);
    cudaGetSymbolAddress((void**)&efah, g_efah);
    cudaGetSymbolAddress((void**)&efal, g_efal);
    cudaGetSymbolAddress((void**)&efbh, g_efbh);
    cudaGetSymbolAddress((void**)&efbl, g_efbl);
    cudaGetSymbolAddress((void**)&node_out, g_node_out);
    cudaGetSymbolAddress((void**)&elog, g_elog);
    cudaGetSymbolAddress((void**)&bcat, g_bcat);
    cudaGetSymbolAddress((void**)&btnh, g_btn_hi);
    cudaGetSymbolAddress((void**)&btnl, g_btn_lo);
    cudaGetSymbolAddress((void**)&bteh, g_bte_hi);
    cudaGetSymbolAddress((void**)&btel, g_bte_lo);
    cudaGetSymbolAddress((void**)&deg, g_deg);
    cudaGetSymbolAddress((void**)&offs, g_offs);
    cudaGetSymbolAddress((void**)&cursor, g_cursor);
    cudaGetSymbolAddress((void**)&eidx, g_eidx);
    cudaGetSymbolAddress((void**)&bsum, g_bsum);

    cudaFuncSetAttribute(gemm_node_mma, cudaFuncAttributeMaxDynamicSharedMemorySize, NODE_SMEM);
    cudaFuncSetAttribute(gemm_edge_mma, cudaFuncAttributeMaxDynamicSharedMemorySize, EDGE_SMEM);

    float* out_nf = (float*)d_out;
    float* out_ef = out_nf + (size_t)NN * 256;

    k_embed<<<(NN * 32 + 255) / 256, 256>>>(node_types, embed, nfh, nfl);
    k_split_ef<<<(EE * 16 + 255) / 256, 256>>>(efeats, efah, efal);

    // CSR by dst (edges identical across layers)
    k_zero_deg<<<NB_SCAN, 256>>>(deg);
    k_hist<<<(EE + 255) / 256, 256>>>(dst, deg);
    k_scanA<<<NB_SCAN, 256>>>(deg, bsum);
    k_scanB<<<1, 256>>>(bsum);
    k_scanC<<<NB_SCAN, 256>>>(deg, bsum, offs, cursor);
    k_scatter<<<(EE + 255) / 256, 256>>>(dst, cursor, eidx);

    for (int L = 0; L < 2; L++) {
        int in_n = L ? 256 : 128;
        int in_e = L ? 128 : 64;
        int prep_items = 512 * in_n + 128 * in_e;
        k_prep<<<(prep_items + 255) / 256, 256>>>(W_ni[L], W_nj[L], W_src[L], b_src[L],
                                                  W_fij[L], bcat, btnh, btnl, bteh, btel,
                                                  in_n, in_e);

        dim3 gn((NN + 127) / 128, 4);
        gemm_node_mma<<<gn, 256, NODE_SMEM>>>(nfh, nfl, btnh, btnl, bcat, node_out, NN, in_n);

        const __nv_bfloat16* eah = L ? efbh : efah;
        const __nv_bfloat16* eal = L ? efbl : efal;
        gemm_edge_mma<<<(EE + 127) / 128, 256, EDGE_SMEM>>>(
            eah, eal, bteh, btel, node_out, src, dst, bias[L], attn[L],
            out_ef, efbh, efbl, elog, EE, in_e, L == 0 ? 0 : 1);

        k_aggr<<<(NN * 32 + 255) / 256, 256>>>(src, eidx, offs, elog, node_out,
                                               out_nf, nfh, nfl, L == 0 ? 0 : 1);
    }
}